// round 2
// baseline (speedup 1.0000x reference)
#include <cuda_runtime.h>
#include <math.h>

// ---------------- problem constants ----------------
#define DIMC   1024
#define B_     4
#define N_     4096
#define T_     256
#define H_     16
#define D_     64
#define INNER_ 1024
#define TK_    257       // T + 1 null token
#define TKP_   260       // padded score row stride (multiple of 4)
#define ROWS_X (B_*N_)   // 16384
#define ROWS_C (B_*T_)   // 1024

// ---------------- device scratch (static, no allocations) ----------------
__device__ float g_xn[(size_t)ROWS_X*DIMC];          // 64 MB  LN(x)
__device__ float g_cn[(size_t)ROWS_C*DIMC];          //  4 MB  LN(context)
__device__ float g_q [(size_t)ROWS_X*INNER_];        // 64 MB  Q (then normalized in place)
__device__ float g_kv[(size_t)ROWS_C*2*INNER_];      //  8 MB  KV proj
__device__ float g_k [(size_t)B_*H_*TK_*D_];         //  4 MB  K normalized + null
__device__ float g_v [(size_t)B_*H_*TK_*D_];         //  4 MB  V + null
__device__ float g_S [(size_t)B_*H_*N_*TKP_];        // 272 MB scores / probs
__device__ float g_ao[(size_t)ROWS_X*INNER_];        // 64 MB  attention output (b,n,h*d)
__device__ float g_pr[(size_t)ROWS_X*DIMC];          // 64 MB  O-proj output

// ---------------- LayerNorm: one block per row of 1024 ----------------
__global__ __launch_bounds__(256)
void ln_kernel(const float* __restrict__ x, const float* __restrict__ g,
               const float* __restrict__ bb, float* __restrict__ y)
{
    int row = blockIdx.x;
    int t   = threadIdx.x;                 // 256 threads * float4 = 1024
    const float4* xr = (const float4*)(x + (size_t)row * DIMC);
    float4 v = xr[t];
    float s1 = v.x + v.y + v.z + v.w;
    float s2 = v.x*v.x + v.y*v.y + v.z*v.z + v.w*v.w;
    #pragma unroll
    for (int o = 16; o; o >>= 1) {
        s1 += __shfl_xor_sync(0xffffffffu, s1, o);
        s2 += __shfl_xor_sync(0xffffffffu, s2, o);
    }
    __shared__ float sh1[8], sh2[8];
    int warp = t >> 5, lane = t & 31;
    if (lane == 0) { sh1[warp] = s1; sh2[warp] = s2; }
    __syncthreads();
    if (warp == 0) {
        s1 = (lane < 8) ? sh1[lane] : 0.f;
        s2 = (lane < 8) ? sh2[lane] : 0.f;
        #pragma unroll
        for (int o = 4; o; o >>= 1) {
            s1 += __shfl_xor_sync(0xffffffffu, s1, o);
            s2 += __shfl_xor_sync(0xffffffffu, s2, o);
        }
        if (lane == 0) {
            float mean = s1 * (1.0f / DIMC);
            float var  = s2 * (1.0f / DIMC) - mean * mean;
            sh1[0] = mean;
            sh2[0] = rsqrtf(var + 1e-5f);
        }
    }
    __syncthreads();
    float mean = sh1[0], rstd = sh2[0];
    float4 gv = ((const float4*)g)[t];
    float4 bv = ((const float4*)bb)[t];
    float4 o4;
    o4.x = (v.x - mean) * rstd * gv.x + bv.x;
    o4.y = (v.y - mean) * rstd * gv.y + bv.y;
    o4.z = (v.z - mean) * rstd * gv.z + bv.z;
    o4.w = (v.w - mean) * rstd * gv.w + bv.w;
    ((float4*)(y + (size_t)row * DIMC))[t] = o4;
}

// ---------------- generic SGEMM: C[M,Nc] = A[M,K] @ W[K,Nc] ----------------
// M%64==0, K%16==0, Nc%64==0, all row-major contiguous. 64x64 tile, 4x4/thread.
__global__ __launch_bounds__(256)
void gemm64(const float* __restrict__ A, const float* __restrict__ W,
            float* __restrict__ C, int K, int Nc)
{
    __shared__ float As[16][68];
    __shared__ float Ws[16][68];
    int tid = threadIdx.x;
    int m0 = blockIdx.y * 64, n0 = blockIdx.x * 64;
    int tx = tid & 15, ty = tid >> 4;
    int amr = tid >> 2, akq = tid & 3;       // A tile: 64 rows x 4 float4
    int wkr = tid >> 4, wnq = tid & 15;      // W tile: 16 rows x 16 float4
    float acc[4][4] = {};
    const float* Abase = A + (size_t)(m0 + amr) * K + akq * 4;
    const float* Wbase = W + (size_t)wkr * Nc + n0 + wnq * 4;

    for (int k0 = 0; k0 < K; k0 += 16) {
        float4 av = *(const float4*)(Abase + k0);
        float4 wv = *(const float4*)(Wbase + (size_t)k0 * Nc);
        __syncthreads();
        As[akq*4+0][amr] = av.x; As[akq*4+1][amr] = av.y;
        As[akq*4+2][amr] = av.z; As[akq*4+3][amr] = av.w;
        *(float4*)&Ws[wkr][wnq*4] = wv;
        __syncthreads();
        #pragma unroll
        for (int k = 0; k < 16; k++) {
            float4 a = *(const float4*)&As[k][ty*4];
            float4 b = *(const float4*)&Ws[k][tx*4];
            acc[0][0] += a.x*b.x; acc[0][1] += a.x*b.y; acc[0][2] += a.x*b.z; acc[0][3] += a.x*b.w;
            acc[1][0] += a.y*b.x; acc[1][1] += a.y*b.y; acc[1][2] += a.y*b.z; acc[1][3] += a.y*b.w;
            acc[2][0] += a.z*b.x; acc[2][1] += a.z*b.y; acc[2][2] += a.z*b.z; acc[2][3] += a.z*b.w;
            acc[3][0] += a.w*b.x; acc[3][1] += a.w*b.y; acc[3][2] += a.w*b.z; acc[3][3] += a.w*b.w;
        }
    }
    #pragma unroll
    for (int i = 0; i < 4; i++) {
        float4 o4 = make_float4(acc[i][0], acc[i][1], acc[i][2], acc[i][3]);
        *(float4*)&C[(size_t)(m0 + ty*4 + i) * Nc + n0 + tx*4] = o4;
    }
}

// ---------------- per-head L2 normalize Q (in place), * q_scale ----------------
__global__ __launch_bounds__(256)
void qnorm_kernel(float* __restrict__ q, const float* __restrict__ qscale)
{
    int w    = (blockIdx.x * 256 + threadIdx.x) >> 5;   // one warp per (row, head)
    int lane = threadIdx.x & 31;
    int row  = w >> 4;          // 0..16383
    int h    = w & 15;
    float* base = q + (size_t)row * INNER_ + h * 64;
    float a = base[lane], b = base[lane + 32];
    float ss = a*a + b*b;
    #pragma unroll
    for (int o = 16; o; o >>= 1) ss += __shfl_xor_sync(0xffffffffu, ss, o);
    float inv = 1.0f / fmaxf(sqrtf(ss), 1e-12f);
    base[lane]      = a * inv * qscale[lane];
    base[lane + 32] = b * inv * qscale[lane + 32];
}

// ---------------- build K (l2-normalized * k_scale, incl. null) and V ----------------
__global__ __launch_bounds__(256)
void kv_build_kernel(const float* __restrict__ kv, const float* __restrict__ nullkv,
                     const float* __restrict__ kscale,
                     float* __restrict__ kout, float* __restrict__ vout)
{
    int w    = (blockIdx.x * 256 + threadIdx.x) >> 5;   // one warp per (b,h,t)
    int lane = threadIdx.x & 31;
    if (w >= B_ * H_ * TK_) return;
    int bh = w / TK_;
    int t  = w - bh * TK_;
    int b  = bh >> 4, h = bh & 15;
    float k0, k1, v0, v1;
    if (t < T_) {
        const float* src = kv + (size_t)(b * T_ + t) * (2 * INNER_) + h * 64;
        k0 = src[lane];            k1 = src[lane + 32];
        v0 = src[INNER_ + lane];   v1 = src[INNER_ + lane + 32];
    } else {
        k0 = nullkv[lane];         k1 = nullkv[lane + 32];
        v0 = nullkv[64 + lane];    v1 = nullkv[64 + lane + 32];
    }
    float ss = k0*k0 + k1*k1;
    #pragma unroll
    for (int o = 16; o; o >>= 1) ss += __shfl_xor_sync(0xffffffffu, ss, o);
    float inv = 1.0f / fmaxf(sqrtf(ss), 1e-12f);
    size_t o = (size_t)w * 64;
    kout[o + lane]      = k0 * inv * kscale[lane];
    kout[o + lane + 32] = k1 * inv * kscale[lane + 32];
    vout[o + lane]      = v0;
    vout[o + lane + 32] = v1;
}

// ---------------- S[n,t] = sum_d q[n,d] * k[t,d]  (per b,h) ----------------
__global__ __launch_bounds__(256)
void qk_kernel(const float* __restrict__ qv, const float* __restrict__ kk,
               float* __restrict__ S)
{
    __shared__ float Qs[16][68];
    __shared__ float Ks[16][68];
    int tid = threadIdx.x;
    int bh = blockIdx.z;
    int b = bh >> 4, h = bh & 15;
    int n0 = blockIdx.y * 64, t0 = blockIdx.x * 64;
    const float* qb = qv + (size_t)(b * N_) * INNER_ + h * 64;   // q[n][d] = qb[n*INNER_+d]
    const float* kb = kk + (size_t)bh * TK_ * D_;                // k[t][d] = kb[t*64+d]
    float* Sb = S + (size_t)bh * N_ * TKP_;
    int tx = tid & 15, ty = tid >> 4;
    int amr = tid >> 2, akq = tid & 3;
    float acc[4][4] = {};

    for (int d0 = 0; d0 < 64; d0 += 16) {
        float4 q4 = *(const float4*)(qb + (size_t)(n0 + amr) * INNER_ + d0 + akq * 4);
        float4 k4 = make_float4(0.f, 0.f, 0.f, 0.f);
        int trow = t0 + amr;
        if (trow < TK_) k4 = *(const float4*)(kb + trow * 64 + d0 + akq * 4);
        __syncthreads();
        Qs[akq*4+0][amr] = q4.x; Qs[akq*4+1][amr] = q4.y;
        Qs[akq*4+2][amr] = q4.z; Qs[akq*4+3][amr] = q4.w;
        Ks[akq*4+0][amr] = k4.x; Ks[akq*4+1][amr] = k4.y;
        Ks[akq*4+2][amr] = k4.z; Ks[akq*4+3][amr] = k4.w;
        __syncthreads();
        #pragma unroll
        for (int k = 0; k < 16; k++) {
            float4 a = *(const float4*)&Qs[k][ty*4];
            float4 b4 = *(const float4*)&Ks[k][tx*4];
            acc[0][0] += a.x*b4.x; acc[0][1] += a.x*b4.y; acc[0][2] += a.x*b4.z; acc[0][3] += a.x*b4.w;
            acc[1][0] += a.y*b4.x; acc[1][1] += a.y*b4.y; acc[1][2] += a.y*b4.z; acc[1][3] += a.y*b4.w;
            acc[2][0] += a.z*b4.x; acc[2][1] += a.z*b4.y; acc[2][2] += a.z*b4.z; acc[2][3] += a.z*b4.w;
            acc[3][0] += a.w*b4.x; acc[3][1] += a.w*b4.y; acc[3][2] += a.w*b4.z; acc[3][3] += a.w*b4.w;
        }
    }
    #pragma unroll
    for (int i = 0; i < 4; i++)
        #pragma unroll
        for (int j = 0; j < 4; j++) {
            int t = t0 + tx*4 + j;
            if (t < TK_) Sb[(size_t)(n0 + ty*4 + i) * TKP_ + t] = acc[i][j];
        }
}

// ---------------- softmax over t (257) with SCALE=8, one warp per row ----------------
__global__ __launch_bounds__(256)
void softmax_kernel(float* __restrict__ S)
{
    int w    = (blockIdx.x * 256 + threadIdx.x) >> 5;   // row index in [0, B*H*N)
    int lane = threadIdx.x & 31;
    float* row = S + (size_t)w * TKP_;
    float vals[9];
    float m = -1e30f;
    #pragma unroll
    for (int j = 0; j < 9; j++) {
        int t = j * 32 + lane;
        float s = (t < TK_) ? row[t] * 8.0f : -1e30f;
        vals[j] = s;
        m = fmaxf(m, s);
    }
    #pragma unroll
    for (int o = 16; o; o >>= 1) m = fmaxf(m, __shfl_xor_sync(0xffffffffu, m, o));
    float sum = 0.f;
    #pragma unroll
    for (int j = 0; j < 9; j++) {
        float p = expf(vals[j] - m);   // underflows to 0 for padded lanes
        vals[j] = p;
        sum += p;
    }
    #pragma unroll
    for (int o = 16; o; o >>= 1) sum += __shfl_xor_sync(0xffffffffu, sum, o);
    float inv = 1.0f / sum;
    #pragma unroll
    for (int j = 0; j < 9; j++) {
        int t = j * 32 + lane;
        if (t < TK_) row[t] = vals[j] * inv;
    }
}

// ---------------- O[n,d] = sum_t P[n,t] * V[t,d]  (per b,h) ----------------
__global__ __launch_bounds__(256)
void pv_kernel(const float* __restrict__ P, const float* __restrict__ vv,
               float* __restrict__ O)
{
    __shared__ float Ps[16][68];
    __shared__ float Vs[16][68];
    int tid = threadIdx.x;
    int bh = blockIdx.z;
    int b = bh >> 4, h = bh & 15;
    int n0 = blockIdx.y * 64;
    const float* Pb = P + (size_t)bh * N_ * TKP_;
    const float* vb = vv + (size_t)bh * TK_ * D_;
    float* Ob = O + (size_t)(b * N_) * INNER_ + h * 64;
    int tx = tid & 15, ty = tid >> 4;
    int amr = tid >> 2, akq = tid & 3;
    int wkr = tid >> 4, wnq = tid & 15;
    float acc[4][4] = {};

    for (int tc = 0; tc < 272; tc += 16) {        // 17 chunks of 16 cover 257
        float pl[4];
        #pragma unroll
        for (int u = 0; u < 4; u++) {
            int t = tc + akq * 4 + u;
            pl[u] = (t < TK_) ? Pb[(size_t)(n0 + amr) * TKP_ + t] : 0.f;
        }
        float4 v4 = make_float4(0.f, 0.f, 0.f, 0.f);
        int tr = tc + wkr;
        if (tr < TK_) v4 = *(const float4*)(vb + tr * 64 + wnq * 4);
        __syncthreads();
        Ps[akq*4+0][amr] = pl[0]; Ps[akq*4+1][amr] = pl[1];
        Ps[akq*4+2][amr] = pl[2]; Ps[akq*4+3][amr] = pl[3];
        *(float4*)&Vs[wkr][wnq*4] = v4;
        __syncthreads();
        #pragma unroll
        for (int k = 0; k < 16; k++) {
            float4 a = *(const float4*)&Ps[k][ty*4];
            float4 b4 = *(const float4*)&Vs[k][tx*4];
            acc[0][0] += a.x*b4.x; acc[0][1] += a.x*b4.y; acc[0][2] += a.x*b4.z; acc[0][3] += a.x*b4.w;
            acc[1][0] += a.y*b4.x; acc[1][1] += a.y*b4.y; acc[1][2] += a.y*b4.z; acc[1][3] += a.y*b4.w;
            acc[2][0] += a.z*b4.x; acc[2][1] += a.z*b4.y; acc[2][2] += a.z*b4.z; acc[2][3] += a.z*b4.w;
            acc[3][0] += a.w*b4.x; acc[3][1] += a.w*b4.y; acc[3][2] += a.w*b4.z; acc[3][3] += a.w*b4.w;
        }
    }
    #pragma unroll
    for (int i = 0; i < 4; i++) {
        float4 o4 = make_float4(acc[i][0], acc[i][1], acc[i][2], acc[i][3]);
        *(float4*)&Ob[(size_t)(n0 + ty*4 + i) * INNER_ + tx*4] = o4;
    }
}

// ---------------- launch ----------------
extern "C" void kernel_launch(void* const* d_in, const int* in_sizes, int n_in,
                              void* d_out, int out_size)
{
    const float* x      = (const float*)d_in[0];
    const float* ctx    = (const float*)d_in[1];
    const float* Wq     = (const float*)d_in[2];
    const float* Wkv    = (const float*)d_in[3];
    const float* Wo     = (const float*)d_in[4];
    const float* nullkv = (const float*)d_in[5];
    const float* qscale = (const float*)d_in[6];
    const float* kscale = (const float*)d_in[7];
    const float* ln_in_g  = (const float*)d_in[8];
    const float* ln_in_b  = (const float*)d_in[9];
    const float* ln_ctx_g = (const float*)d_in[10];
    const float* ln_ctx_b = (const float*)d_in[11];
    const float* ln_out_g = (const float*)d_in[12];
    const float* ln_out_b = (const float*)d_in[13];
    float* out = (float*)d_out;

    float *p_xn, *p_cn, *p_q, *p_kv, *p_k, *p_v, *p_S, *p_ao, *p_pr;
    cudaGetSymbolAddress((void**)&p_xn, g_xn);
    cudaGetSymbolAddress((void**)&p_cn, g_cn);
    cudaGetSymbolAddress((void**)&p_q,  g_q);
    cudaGetSymbolAddress((void**)&p_kv, g_kv);
    cudaGetSymbolAddress((void**)&p_k,  g_k);
    cudaGetSymbolAddress((void**)&p_v,  g_v);
    cudaGetSymbolAddress((void**)&p_S,  g_S);
    cudaGetSymbolAddress((void**)&p_ao, g_ao);
    cudaGetSymbolAddress((void**)&p_pr, g_pr);

    // 1-2: LayerNorms
    ln_kernel<<<ROWS_X, 256>>>(x,   ln_in_g,  ln_in_b,  p_xn);
    ln_kernel<<<ROWS_C, 256>>>(ctx, ln_ctx_g, ln_ctx_b, p_cn);
    // 3-4: projections
    gemm64<<<dim3(INNER_/64,   ROWS_X/64), 256>>>(p_xn, Wq,  p_q,  DIMC, INNER_);
    gemm64<<<dim3(2*INNER_/64, ROWS_C/64), 256>>>(p_cn, Wkv, p_kv, DIMC, 2*INNER_);
    // 5: normalize q per head (in place)
    qnorm_kernel<<<(ROWS_X * H_) / 8, 256>>>(p_q, qscale);
    // 6: build K (normalized, incl null) and V
    kv_build_kernel<<<(B_*H_*TK_ + 7) / 8, 256>>>(p_kv, nullkv, kscale, p_k, p_v);
    // 7: scores
    qk_kernel<<<dim3((TK_ + 63)/64, N_/64, B_*H_), 256>>>(p_q, p_k, p_S);
    // 8: softmax (SCALE folded in)
    softmax_kernel<<<(B_*H_*N_) / 8, 256>>>(p_S);
    // 9: attention output
    pv_kernel<<<dim3(1, N_/64, B_*H_), 256>>>(p_S, p_v, p_ao);
    // 10: output projection
    gemm64<<<dim3(DIMC/64, ROWS_X/64), 256>>>(p_ao, Wo, p_pr, INNER_, DIMC);
    // 11: final LN -> d_out
    ln_kernel<<<ROWS_X, 256>>>(p_pr, ln_out_g, ln_out_b, out);
}

// round 3
// speedup vs baseline: 2.0030x; 2.0030x over previous
#include <cuda_runtime.h>
#include <math.h>

// ---------------- problem constants ----------------
#define DIMC   1024
#define B_     4
#define N_     4096
#define T_     256
#define H_     16
#define D_     64
#define INNER_ 1024
#define TK_    257       // T + 1 null token
#define TKP_   260       // padded score row stride (multiple of 4)
#define ROWS_X (B_*N_)   // 16384
#define ROWS_C (B_*T_)   // 1024

// ---------------- device scratch (static, no allocations) ----------------
__device__ float g_xn[(size_t)ROWS_X*DIMC];
__device__ float g_cn[(size_t)ROWS_C*DIMC];
__device__ float g_q [(size_t)ROWS_X*INNER_];
__device__ float g_kv[(size_t)ROWS_C*2*INNER_];
__device__ float g_k [(size_t)B_*H_*TK_*D_];
__device__ float g_v [(size_t)B_*H_*TK_*D_];
__device__ float g_S [(size_t)B_*H_*N_*TKP_];
__device__ float g_ao[(size_t)ROWS_X*INNER_];
__device__ float g_pr[(size_t)ROWS_X*DIMC];

// ---------------- tf32 helpers ----------------
__device__ __forceinline__ unsigned f2tf32(float x) {
    unsigned u;
    asm("cvt.rna.tf32.f32 %0, %1;" : "=r"(u) : "f"(x));
    return u;
}
__device__ __forceinline__ void mma_tf32(float c[4], const unsigned a[4], const unsigned b[2]) {
    asm volatile(
        "mma.sync.aligned.m16n8k8.row.col.f32.tf32.tf32.f32 "
        "{%0,%1,%2,%3}, {%4,%5,%6,%7}, {%8,%9}, {%0,%1,%2,%3};"
        : "+f"(c[0]), "+f"(c[1]), "+f"(c[2]), "+f"(c[3])
        : "r"(a[0]), "r"(a[1]), "r"(a[2]), "r"(a[3]), "r"(b[0]), "r"(b[1]));
}

// ---------------- LayerNorm: one block per row of 1024 ----------------
__global__ __launch_bounds__(256)
void ln_kernel(const float* __restrict__ x, const float* __restrict__ g,
               const float* __restrict__ bb, float* __restrict__ y)
{
    int row = blockIdx.x;
    int t   = threadIdx.x;
    const float4* xr = (const float4*)(x + (size_t)row * DIMC);
    float4 v = xr[t];
    float s1 = v.x + v.y + v.z + v.w;
    float s2 = v.x*v.x + v.y*v.y + v.z*v.z + v.w*v.w;
    #pragma unroll
    for (int o = 16; o; o >>= 1) {
        s1 += __shfl_xor_sync(0xffffffffu, s1, o);
        s2 += __shfl_xor_sync(0xffffffffu, s2, o);
    }
    __shared__ float sh1[8], sh2[8];
    int warp = t >> 5, lane = t & 31;
    if (lane == 0) { sh1[warp] = s1; sh2[warp] = s2; }
    __syncthreads();
    if (warp == 0) {
        s1 = (lane < 8) ? sh1[lane] : 0.f;
        s2 = (lane < 8) ? sh2[lane] : 0.f;
        #pragma unroll
        for (int o = 4; o; o >>= 1) {
            s1 += __shfl_xor_sync(0xffffffffu, s1, o);
            s2 += __shfl_xor_sync(0xffffffffu, s2, o);
        }
        if (lane == 0) {
            float mean = s1 * (1.0f / DIMC);
            float var  = s2 * (1.0f / DIMC) - mean * mean;
            sh1[0] = mean;
            sh2[0] = rsqrtf(var + 1e-5f);
        }
    }
    __syncthreads();
    float mean = sh1[0], rstd = sh2[0];
    float4 gv = ((const float4*)g)[t];
    float4 bv = ((const float4*)bb)[t];
    float4 o4;
    o4.x = (v.x - mean) * rstd * gv.x + bv.x;
    o4.y = (v.y - mean) * rstd * gv.y + bv.y;
    o4.z = (v.z - mean) * rstd * gv.z + bv.z;
    o4.w = (v.w - mean) * rstd * gv.w + bv.w;
    ((float4*)(y + (size_t)row * DIMC))[t] = o4;
}

// ---------------- tensor-core SGEMM (tf32): C[M,Nc] = A[M,K] @ W[K,Nc] ----------------
// M%128==0, K%32==0, Nc%128==0. Block tile 128x128x32, 8 warps (4M x 2N), warp 32x64.
__global__ __launch_bounds__(256)
void gemm_tc(const float* __restrict__ A, const float* __restrict__ W,
             float* __restrict__ C, int K, int Nc)
{
    __shared__ unsigned As[32][132];   // [k][m]
    __shared__ unsigned Bs[32][132];   // [k][n]
    int tid = threadIdx.x, lane = tid & 31, warp = tid >> 5;
    int m0 = blockIdx.y * 128, n0 = blockIdx.x * 128;
    int wm = warp & 3, wn = warp >> 2;        // warp tile: rows wm*32, cols wn*64
    float c[2][8][4] = {};

    int ar = tid >> 3, acq = tid & 7;         // A: 8 float4 per row
    int br = tid >> 5, bcq = tid & 31;        // B: 32 float4 per row

    float4 aReg[4], bReg[4];
    const int kIters = K >> 5;

    // preload k0 = 0
    #pragma unroll
    for (int i = 0; i < 4; i++) {
        aReg[i] = *(const float4*)&A[(size_t)(m0 + ar + i*32) * K + acq*4];
        bReg[i] = *(const float4*)&W[(size_t)(br + i*8) * Nc + n0 + bcq*4];
    }
    #pragma unroll
    for (int i = 0; i < 4; i++) {
        As[acq*4+0][ar + i*32] = f2tf32(aReg[i].x);
        As[acq*4+1][ar + i*32] = f2tf32(aReg[i].y);
        As[acq*4+2][ar + i*32] = f2tf32(aReg[i].z);
        As[acq*4+3][ar + i*32] = f2tf32(aReg[i].w);
        uint4 bw = make_uint4(f2tf32(bReg[i].x), f2tf32(bReg[i].y),
                              f2tf32(bReg[i].z), f2tf32(bReg[i].w));
        *(uint4*)&Bs[br + i*8][bcq*4] = bw;
    }
    __syncthreads();

    for (int ki = 0; ki < kIters; ki++) {
        bool more = (ki + 1) < kIters;
        if (more) {
            int k0 = (ki + 1) << 5;
            #pragma unroll
            for (int i = 0; i < 4; i++) {
                aReg[i] = *(const float4*)&A[(size_t)(m0 + ar + i*32) * K + k0 + acq*4];
                bReg[i] = *(const float4*)&W[(size_t)(k0 + br + i*8) * Nc + n0 + bcq*4];
            }
        }
        #pragma unroll
        for (int ks = 0; ks < 4; ks++) {
            int kk = ks * 8;
            unsigned af[2][4];
            #pragma unroll
            for (int mt = 0; mt < 2; mt++) {
                int m = wm*32 + mt*16 + (lane >> 2);
                int ck = kk + (lane & 3);
                af[mt][0] = As[ck][m];
                af[mt][1] = As[ck][m + 8];
                af[mt][2] = As[ck + 4][m];
                af[mt][3] = As[ck + 4][m + 8];
            }
            unsigned bf[8][2];
            #pragma unroll
            for (int nt = 0; nt < 8; nt++) {
                int n = wn*64 + nt*8 + (lane >> 2);
                bf[nt][0] = Bs[kk + (lane & 3)][n];
                bf[nt][1] = Bs[kk + 4 + (lane & 3)][n];
            }
            #pragma unroll
            for (int mt = 0; mt < 2; mt++)
                #pragma unroll
                for (int nt = 0; nt < 8; nt++)
                    mma_tf32(c[mt][nt], af[mt], bf[nt]);
        }
        __syncthreads();
        if (more) {
            #pragma unroll
            for (int i = 0; i < 4; i++) {
                As[acq*4+0][ar + i*32] = f2tf32(aReg[i].x);
                As[acq*4+1][ar + i*32] = f2tf32(aReg[i].y);
                As[acq*4+2][ar + i*32] = f2tf32(aReg[i].z);
                As[acq*4+3][ar + i*32] = f2tf32(aReg[i].w);
                uint4 bw = make_uint4(f2tf32(bReg[i].x), f2tf32(bReg[i].y),
                                      f2tf32(bReg[i].z), f2tf32(bReg[i].w));
                *(uint4*)&Bs[br + i*8][bcq*4] = bw;
            }
            __syncthreads();
        }
    }

    #pragma unroll
    for (int mt = 0; mt < 2; mt++) {
        int row = m0 + wm*32 + mt*16 + (lane >> 2);
        #pragma unroll
        for (int nt = 0; nt < 8; nt++) {
            int col = n0 + wn*64 + nt*8 + 2*(lane & 3);
            *(float2*)&C[(size_t)row * Nc + col]       = make_float2(c[mt][nt][0], c[mt][nt][1]);
            *(float2*)&C[(size_t)(row + 8) * Nc + col] = make_float2(c[mt][nt][2], c[mt][nt][3]);
        }
    }
}

// ---------------- per-head L2 normalize Q (in place), * q_scale ----------------
__global__ __launch_bounds__(256)
void qnorm_kernel(float* __restrict__ q, const float* __restrict__ qscale)
{
    int w    = (blockIdx.x * 256 + threadIdx.x) >> 5;
    int lane = threadIdx.x & 31;
    int row  = w >> 4;
    int h    = w & 15;
    float* base = q + (size_t)row * INNER_ + h * 64;
    float a = base[lane], b = base[lane + 32];
    float ss = a*a + b*b;
    #pragma unroll
    for (int o = 16; o; o >>= 1) ss += __shfl_xor_sync(0xffffffffu, ss, o);
    float inv = 1.0f / fmaxf(sqrtf(ss), 1e-12f);
    base[lane]      = a * inv * qscale[lane];
    base[lane + 32] = b * inv * qscale[lane + 32];
}

// ---------------- build K (l2-normalized * k_scale, incl. null) and V ----------------
__global__ __launch_bounds__(256)
void kv_build_kernel(const float* __restrict__ kv, const float* __restrict__ nullkv,
                     const float* __restrict__ kscale,
                     float* __restrict__ kout, float* __restrict__ vout)
{
    int w    = (blockIdx.x * 256 + threadIdx.x) >> 5;
    int lane = threadIdx.x & 31;
    if (w >= B_ * H_ * TK_) return;
    int bh = w / TK_;
    int t  = w - bh * TK_;
    int b  = bh >> 4, h = bh & 15;
    float k0, k1, v0, v1;
    if (t < T_) {
        const float* src = kv + (size_t)(b * T_ + t) * (2 * INNER_) + h * 64;
        k0 = src[lane];            k1 = src[lane + 32];
        v0 = src[INNER_ + lane];   v1 = src[INNER_ + lane + 32];
    } else {
        k0 = nullkv[lane];         k1 = nullkv[lane + 32];
        v0 = nullkv[64 + lane];    v1 = nullkv[64 + lane + 32];
    }
    float ss = k0*k0 + k1*k1;
    #pragma unroll
    for (int o = 16; o; o >>= 1) ss += __shfl_xor_sync(0xffffffffu, ss, o);
    float inv = 1.0f / fmaxf(sqrtf(ss), 1e-12f);
    size_t o = (size_t)w * 64;
    kout[o + lane]      = k0 * inv * kscale[lane];
    kout[o + lane + 32] = k1 * inv * kscale[lane + 32];
    vout[o + lane]      = v0;
    vout[o + lane + 32] = v1;
}

// ---------------- QK^T (tf32): S[n,t] = sum_d q[n,d]*k[t,d] per (b,h) ----------------
// Block tile 128(n) x 64(t), K=64 in two 32-chunks. 8 warps (4M x 2N), warp 32x32.
__global__ __launch_bounds__(256)
void qk_tc(const float* __restrict__ qv, const float* __restrict__ kk,
           float* __restrict__ S)
{
    __shared__ unsigned As[32][132];   // [d][n]
    __shared__ unsigned Bs[32][68];    // [d][t]
    int tid = threadIdx.x, lane = tid & 31, warp = tid >> 5;
    int bh = blockIdx.z;
    int b = bh >> 4, h = bh & 15;
    int n0 = blockIdx.y * 128, t0 = blockIdx.x * 64;
    const float* qb = qv + (size_t)(b * N_) * INNER_ + h * 64;
    const float* kb = kk + (size_t)bh * TK_ * D_;
    float* Sb = S + (size_t)bh * N_ * TKP_;
    int wm = warp & 3, wn = warp >> 2;
    float c[2][4][4] = {};

    int ar = tid >> 3, acq = tid & 7;     // Q: 128 rows x 8 float4
    for (int d0 = 0; d0 < 64; d0 += 32) {
        __syncthreads();
        #pragma unroll
        for (int i = 0; i < 4; i++) {
            float4 v = *(const float4*)&qb[(size_t)(n0 + ar + i*32) * INNER_ + d0 + acq*4];
            As[acq*4+0][ar + i*32] = f2tf32(v.x);
            As[acq*4+1][ar + i*32] = f2tf32(v.y);
            As[acq*4+2][ar + i*32] = f2tf32(v.z);
            As[acq*4+3][ar + i*32] = f2tf32(v.w);
        }
        #pragma unroll
        for (int i = 0; i < 2; i++) {     // K tile: 64 rows x 8 float4, transposed store
            int l = tid + i*256;
            int tr = l >> 3, cq = l & 7;
            int t = t0 + tr;
            float4 v = make_float4(0.f, 0.f, 0.f, 0.f);
            if (t < TK_) v = *(const float4*)&kb[(size_t)t * 64 + d0 + cq*4];
            Bs[cq*4+0][tr] = f2tf32(v.x);
            Bs[cq*4+1][tr] = f2tf32(v.y);
            Bs[cq*4+2][tr] = f2tf32(v.z);
            Bs[cq*4+3][tr] = f2tf32(v.w);
        }
        __syncthreads();
        #pragma unroll
        for (int ks = 0; ks < 4; ks++) {
            int kd = ks * 8;
            unsigned af[2][4];
            #pragma unroll
            for (int mt = 0; mt < 2; mt++) {
                int m = wm*32 + mt*16 + (lane >> 2);
                int ck = kd + (lane & 3);
                af[mt][0] = As[ck][m];
                af[mt][1] = As[ck][m + 8];
                af[mt][2] = As[ck + 4][m];
                af[mt][3] = As[ck + 4][m + 8];
            }
            unsigned bf[4][2];
            #pragma unroll
            for (int nt = 0; nt < 4; nt++) {
                int n = wn*32 + nt*8 + (lane >> 2);
                bf[nt][0] = Bs[kd + (lane & 3)][n];
                bf[nt][1] = Bs[kd + 4 + (lane & 3)][n];
            }
            #pragma unroll
            for (int mt = 0; mt < 2; mt++)
                #pragma unroll
                for (int nt = 0; nt < 4; nt++)
                    mma_tf32(c[mt][nt], af[mt], bf[nt]);
        }
    }

    #pragma unroll
    for (int mt = 0; mt < 2; mt++) {
        int row = n0 + wm*32 + mt*16 + (lane >> 2);
        #pragma unroll
        for (int nt = 0; nt < 4; nt++) {
            int t = t0 + wn*32 + nt*8 + 2*(lane & 3);
            if (t < TK_)     Sb[(size_t)row * TKP_ + t]           = c[mt][nt][0];
            if (t + 1 < TK_) Sb[(size_t)row * TKP_ + t + 1]       = c[mt][nt][1];
            if (t < TK_)     Sb[(size_t)(row + 8) * TKP_ + t]     = c[mt][nt][2];
            if (t + 1 < TK_) Sb[(size_t)(row + 8) * TKP_ + t + 1] = c[mt][nt][3];
        }
    }
}

// ---------------- softmax over t (257) with SCALE=8, one warp per row ----------------
__global__ __launch_bounds__(256)
void softmax_kernel(float* __restrict__ S)
{
    int w    = (blockIdx.x * 256 + threadIdx.x) >> 5;
    int lane = threadIdx.x & 31;
    float* row = S + (size_t)w * TKP_;
    float vals[9];
    float m = -1e30f;
    #pragma unroll
    for (int j = 0; j < 9; j++) {
        int t = j * 32 + lane;
        float s = (t < TK_) ? row[t] * 8.0f : -1e30f;
        vals[j] = s;
        m = fmaxf(m, s);
    }
    #pragma unroll
    for (int o = 16; o; o >>= 1) m = fmaxf(m, __shfl_xor_sync(0xffffffffu, m, o));
    float sum = 0.f;
    #pragma unroll
    for (int j = 0; j < 9; j++) {
        float p = expf(vals[j] - m);
        vals[j] = p;
        sum += p;
    }
    #pragma unroll
    for (int o = 16; o; o >>= 1) sum += __shfl_xor_sync(0xffffffffu, sum, o);
    float inv = 1.0f / sum;
    #pragma unroll
    for (int j = 0; j < 9; j++) {
        int t = j * 32 + lane;
        if (t < TK_) row[t] = vals[j] * inv;
    }
}

// ---------------- PV (tf32): O[n,d] = sum_t P[n,t]*V[t,d] per (b,h) ----------------
// Block tile 128(n) x 64(d), t loop in 16-chunks (17 iters). Warp 32x32.
__global__ __launch_bounds__(256)
void pv_tc(const float* __restrict__ P, const float* __restrict__ vv,
           float* __restrict__ O)
{
    __shared__ unsigned As[16][132];   // [t][n]
    __shared__ unsigned Bs[16][68];    // [t][d]
    int tid = threadIdx.x, lane = tid & 31, warp = tid >> 5;
    int bh = blockIdx.z;
    int b = bh >> 4, h = bh & 15;
    int n0 = blockIdx.y * 128;
    const float* Pb = P + (size_t)bh * N_ * TKP_;
    const float* vb = vv + (size_t)bh * TK_ * D_;
    float* Ob = O + (size_t)(b * N_) * INNER_ + h * 64;
    int wm = warp & 3, wn = warp >> 2;
    float c[2][4][4] = {};

    for (int tc = 0; tc < 272; tc += 16) {
        __syncthreads();
        #pragma unroll
        for (int i = 0; i < 2; i++) {   // P tile: 128 rows x 4 float4, transposed
            int l = tid + i*256;
            int r = l >> 2, cq = l & 3;
            #pragma unroll
            for (int j = 0; j < 4; j++) {
                int t = tc + cq*4 + j;
                float v = (t < TK_) ? Pb[(size_t)(n0 + r) * TKP_ + t] : 0.f;
                As[cq*4+j][r] = f2tf32(v);
            }
        }
        {                               // V tile: 16 rows x 16 float4
            int r = tid >> 4, cq = tid & 15;
            int t = tc + r;
            float4 v = make_float4(0.f, 0.f, 0.f, 0.f);
            if (t < TK_) v = *(const float4*)&vb[(size_t)t * 64 + cq*4];
            Bs[r][cq*4+0] = f2tf32(v.x);
            Bs[r][cq*4+1] = f2tf32(v.y);
            Bs[r][cq*4+2] = f2tf32(v.z);
            Bs[r][cq*4+3] = f2tf32(v.w);
        }
        __syncthreads();
        #pragma unroll
        for (int ks = 0; ks < 2; ks++) {
            int kt = ks * 8;
            unsigned af[2][4];
            #pragma unroll
            for (int mt = 0; mt < 2; mt++) {
                int m = wm*32 + mt*16 + (lane >> 2);
                int ck = kt + (lane & 3);
                af[mt][0] = As[ck][m];
                af[mt][1] = As[ck][m + 8];
                af[mt][2] = As[ck + 4][m];
                af[mt][3] = As[ck + 4][m + 8];
            }
            unsigned bf[4][2];
            #pragma unroll
            for (int nt = 0; nt < 4; nt++) {
                int n = wn*32 + nt*8 + (lane >> 2);
                bf[nt][0] = Bs[kt + (lane & 3)][n];
                bf[nt][1] = Bs[kt + 4 + (lane & 3)][n];
            }
            #pragma unroll
            for (int mt = 0; mt < 2; mt++)
                #pragma unroll
                for (int nt = 0; nt < 4; nt++)
                    mma_tf32(c[mt][nt], af[mt], bf[nt]);
        }
    }

    #pragma unroll
    for (int mt = 0; mt < 2; mt++) {
        int row = n0 + wm*32 + mt*16 + (lane >> 2);
        #pragma unroll
        for (int nt = 0; nt < 4; nt++) {
            int col = wn*32 + nt*8 + 2*(lane & 3);
            *(float2*)&Ob[(size_t)row * INNER_ + col]       = make_float2(c[mt][nt][0], c[mt][nt][1]);
            *(float2*)&Ob[(size_t)(row + 8) * INNER_ + col] = make_float2(c[mt][nt][2], c[mt][nt][3]);
        }
    }
}

// ---------------- launch ----------------
extern "C" void kernel_launch(void* const* d_in, const int* in_sizes, int n_in,
                              void* d_out, int out_size)
{
    const float* x      = (const float*)d_in[0];
    const float* ctx    = (const float*)d_in[1];
    const float* Wq     = (const float*)d_in[2];
    const float* Wkv    = (const float*)d_in[3];
    const float* Wo     = (const float*)d_in[4];
    const float* nullkv = (const float*)d_in[5];
    const float* qscale = (const float*)d_in[6];
    const float* kscale = (const float*)d_in[7];
    const float* ln_in_g  = (const float*)d_in[8];
    const float* ln_in_b  = (const float*)d_in[9];
    const float* ln_ctx_g = (const float*)d_in[10];
    const float* ln_ctx_b = (const float*)d_in[11];
    const float* ln_out_g = (const float*)d_in[12];
    const float* ln_out_b = (const float*)d_in[13];
    float* out = (float*)d_out;

    float *p_xn, *p_cn, *p_q, *p_kv, *p_k, *p_v, *p_S, *p_ao, *p_pr;
    cudaGetSymbolAddress((void**)&p_xn, g_xn);
    cudaGetSymbolAddress((void**)&p_cn, g_cn);
    cudaGetSymbolAddress((void**)&p_q,  g_q);
    cudaGetSymbolAddress((void**)&p_kv, g_kv);
    cudaGetSymbolAddress((void**)&p_k,  g_k);
    cudaGetSymbolAddress((void**)&p_v,  g_v);
    cudaGetSymbolAddress((void**)&p_S,  g_S);
    cudaGetSymbolAddress((void**)&p_ao, g_ao);
    cudaGetSymbolAddress((void**)&p_pr, g_pr);

    // 1-2: LayerNorms
    ln_kernel<<<ROWS_X, 256>>>(x,   ln_in_g,  ln_in_b,  p_xn);
    ln_kernel<<<ROWS_C, 256>>>(ctx, ln_ctx_g, ln_ctx_b, p_cn);
    // 3-4: projections (tf32 tensor cores)
    gemm_tc<<<dim3(INNER_/128,   ROWS_X/128), 256>>>(p_xn, Wq,  p_q,  DIMC, INNER_);
    gemm_tc<<<dim3(2*INNER_/128, ROWS_C/128), 256>>>(p_cn, Wkv, p_kv, DIMC, 2*INNER_);
    // 5: normalize q per head (in place)
    qnorm_kernel<<<(ROWS_X * H_) / 8, 256>>>(p_q, qscale);
    // 6: build K (normalized, incl null) and V
    kv_build_kernel<<<(B_*H_*TK_ + 7) / 8, 256>>>(p_kv, nullkv, kscale, p_k, p_v);
    // 7: scores (tf32)
    qk_tc<<<dim3((TK_ + 63)/64, N_/128, B_*H_), 256>>>(p_q, p_k, p_S);
    // 8: softmax (SCALE folded in)
    softmax_kernel<<<(B_*H_*N_) / 8, 256>>>(p_S);
    // 9: attention output (tf32)
    pv_tc<<<dim3(1, N_/128, B_*H_), 256>>>(p_S, p_v, p_ao);
    // 10: output projection (tf32)
    gemm_tc<<<dim3(DIMC/128, ROWS_X/128), 256>>>(p_ao, Wo, p_pr, INNER_, DIMC);
    // 11: final LN -> d_out
    ln_kernel<<<ROWS_X, 256>>>(p_pr, ln_out_g, ln_out_b, out);
}

// round 4
// speedup vs baseline: 2.4911x; 1.2436x over previous
#include <cuda_runtime.h>
#include <math.h>

// ---------------- problem constants ----------------
#define DIMC   1024
#define B_     4
#define N_     4096
#define T_     256
#define H_     16
#define D_     64
#define INNER_ 1024
#define TK_    257       // T + 1 null token
#define ROWS_X (B_*N_)   // 16384
#define ROWS_C (B_*T_)   // 1024

// ---------------- device scratch (static, no allocations) ----------------
__device__ float g_xn[(size_t)ROWS_X*DIMC];
__device__ float g_cn[(size_t)ROWS_C*DIMC];
__device__ float g_q [(size_t)ROWS_X*INNER_];
__device__ float g_kv[(size_t)ROWS_C*2*INNER_];
__device__ float g_k [(size_t)B_*H_*TK_*D_];
__device__ float g_v [(size_t)B_*H_*TK_*D_];
__device__ float g_ao[(size_t)ROWS_X*INNER_];
__device__ float g_pr[(size_t)ROWS_X*DIMC];

// ---------------- tf32 helpers ----------------
__device__ __forceinline__ unsigned f2tf32(float x) {
    unsigned u;
    asm("cvt.rna.tf32.f32 %0, %1;" : "=r"(u) : "f"(x));
    return u;
}
__device__ __forceinline__ void mma_tf32(float c[4], const unsigned a[4], const unsigned b[2]) {
    asm volatile(
        "mma.sync.aligned.m16n8k8.row.col.f32.tf32.tf32.f32 "
        "{%0,%1,%2,%3}, {%4,%5,%6,%7}, {%8,%9}, {%0,%1,%2,%3};"
        : "+f"(c[0]), "+f"(c[1]), "+f"(c[2]), "+f"(c[3])
        : "r"(a[0]), "r"(a[1]), "r"(a[2]), "r"(a[3]), "r"(b[0]), "r"(b[1]));
}

// ---------------- LayerNorm: one block per row of 1024 ----------------
__global__ __launch_bounds__(256)
void ln_kernel(const float* __restrict__ x, const float* __restrict__ g,
               const float* __restrict__ bb, float* __restrict__ y)
{
    int row = blockIdx.x;
    int t   = threadIdx.x;
    const float4* xr = (const float4*)(x + (size_t)row * DIMC);
    float4 v = xr[t];
    float s1 = v.x + v.y + v.z + v.w;
    float s2 = v.x*v.x + v.y*v.y + v.z*v.z + v.w*v.w;
    #pragma unroll
    for (int o = 16; o; o >>= 1) {
        s1 += __shfl_xor_sync(0xffffffffu, s1, o);
        s2 += __shfl_xor_sync(0xffffffffu, s2, o);
    }
    __shared__ float sh1[8], sh2[8];
    int warp = t >> 5, lane = t & 31;
    if (lane == 0) { sh1[warp] = s1; sh2[warp] = s2; }
    __syncthreads();
    if (warp == 0) {
        s1 = (lane < 8) ? sh1[lane] : 0.f;
        s2 = (lane < 8) ? sh2[lane] : 0.f;
        #pragma unroll
        for (int o = 4; o; o >>= 1) {
            s1 += __shfl_xor_sync(0xffffffffu, s1, o);
            s2 += __shfl_xor_sync(0xffffffffu, s2, o);
        }
        if (lane == 0) {
            float mean = s1 * (1.0f / DIMC);
            float var  = s2 * (1.0f / DIMC) - mean * mean;
            sh1[0] = mean;
            sh2[0] = rsqrtf(var + 1e-5f);
        }
    }
    __syncthreads();
    float mean = sh1[0], rstd = sh2[0];
    float4 gv = ((const float4*)g)[t];
    float4 bv = ((const float4*)bb)[t];
    float4 o4;
    o4.x = (v.x - mean) * rstd * gv.x + bv.x;
    o4.y = (v.y - mean) * rstd * gv.y + bv.y;
    o4.z = (v.z - mean) * rstd * gv.z + bv.z;
    o4.w = (v.w - mean) * rstd * gv.w + bv.w;
    ((float4*)(y + (size_t)row * DIMC))[t] = o4;
}

// ---------------- tensor-core SGEMM (tf32): C[M,Nc] = A[M,K] @ W[K,Nc] ----------------
__global__ __launch_bounds__(256, 2)
void gemm_tc(const float* __restrict__ A, const float* __restrict__ W,
             float* __restrict__ C, int K, int Nc)
{
    __shared__ unsigned As[32][132];   // [k][m]
    __shared__ unsigned Bs[32][132];   // [k][n]
    int tid = threadIdx.x, lane = tid & 31, warp = tid >> 5;
    int m0 = blockIdx.y * 128, n0 = blockIdx.x * 128;
    int wm = warp & 3, wn = warp >> 2;
    float c[2][8][4] = {};

    int ar = tid >> 3, acq = tid & 7;
    int br = tid >> 5, bcq = tid & 31;

    float4 aReg[4], bReg[4];
    const int kIters = K >> 5;

    #pragma unroll
    for (int i = 0; i < 4; i++) {
        aReg[i] = *(const float4*)&A[(size_t)(m0 + ar + i*32) * K + acq*4];
        bReg[i] = *(const float4*)&W[(size_t)(br + i*8) * Nc + n0 + bcq*4];
    }
    #pragma unroll
    for (int i = 0; i < 4; i++) {
        As[acq*4+0][ar + i*32] = f2tf32(aReg[i].x);
        As[acq*4+1][ar + i*32] = f2tf32(aReg[i].y);
        As[acq*4+2][ar + i*32] = f2tf32(aReg[i].z);
        As[acq*4+3][ar + i*32] = f2tf32(aReg[i].w);
        uint4 bw = make_uint4(f2tf32(bReg[i].x), f2tf32(bReg[i].y),
                              f2tf32(bReg[i].z), f2tf32(bReg[i].w));
        *(uint4*)&Bs[br + i*8][bcq*4] = bw;
    }
    __syncthreads();

    for (int ki = 0; ki < kIters; ki++) {
        bool more = (ki + 1) < kIters;
        if (more) {
            int k0 = (ki + 1) << 5;
            #pragma unroll
            for (int i = 0; i < 4; i++) {
                aReg[i] = *(const float4*)&A[(size_t)(m0 + ar + i*32) * K + k0 + acq*4];
                bReg[i] = *(const float4*)&W[(size_t)(k0 + br + i*8) * Nc + n0 + bcq*4];
            }
        }
        #pragma unroll
        for (int ks = 0; ks < 4; ks++) {
            int kk = ks * 8;
            unsigned af[2][4];
            #pragma unroll
            for (int mt = 0; mt < 2; mt++) {
                int m = wm*32 + mt*16 + (lane >> 2);
                int ck = kk + (lane & 3);
                af[mt][0] = As[ck][m];
                af[mt][1] = As[ck][m + 8];
                af[mt][2] = As[ck + 4][m];
                af[mt][3] = As[ck + 4][m + 8];
            }
            unsigned bf[8][2];
            #pragma unroll
            for (int nt = 0; nt < 8; nt++) {
                int n = wn*64 + nt*8 + (lane >> 2);
                bf[nt][0] = Bs[kk + (lane & 3)][n];
                bf[nt][1] = Bs[kk + 4 + (lane & 3)][n];
            }
            #pragma unroll
            for (int mt = 0; mt < 2; mt++)
                #pragma unroll
                for (int nt = 0; nt < 8; nt++)
                    mma_tf32(c[mt][nt], af[mt], bf[nt]);
        }
        __syncthreads();
        if (more) {
            #pragma unroll
            for (int i = 0; i < 4; i++) {
                As[acq*4+0][ar + i*32] = f2tf32(aReg[i].x);
                As[acq*4+1][ar + i*32] = f2tf32(aReg[i].y);
                As[acq*4+2][ar + i*32] = f2tf32(aReg[i].z);
                As[acq*4+3][ar + i*32] = f2tf32(aReg[i].w);
                uint4 bw = make_uint4(f2tf32(bReg[i].x), f2tf32(bReg[i].y),
                                      f2tf32(bReg[i].z), f2tf32(bReg[i].w));
                *(uint4*)&Bs[br + i*8][bcq*4] = bw;
            }
            __syncthreads();
        }
    }

    #pragma unroll
    for (int mt = 0; mt < 2; mt++) {
        int row = m0 + wm*32 + mt*16 + (lane >> 2);
        #pragma unroll
        for (int nt = 0; nt < 8; nt++) {
            int col = n0 + wn*64 + nt*8 + 2*(lane & 3);
            *(float2*)&C[(size_t)row * Nc + col]       = make_float2(c[mt][nt][0], c[mt][nt][1]);
            *(float2*)&C[(size_t)(row + 8) * Nc + col] = make_float2(c[mt][nt][2], c[mt][nt][3]);
        }
    }
}

// ---------------- per-head L2 normalize Q (in place), * q_scale ----------------
__global__ __launch_bounds__(256)
void qnorm_kernel(float* __restrict__ q, const float* __restrict__ qscale)
{
    int w    = (blockIdx.x * 256 + threadIdx.x) >> 5;
    int lane = threadIdx.x & 31;
    int row  = w >> 4;
    int h    = w & 15;
    float* base = q + (size_t)row * INNER_ + h * 64;
    float a = base[lane], b = base[lane + 32];
    float ss = a*a + b*b;
    #pragma unroll
    for (int o = 16; o; o >>= 1) ss += __shfl_xor_sync(0xffffffffu, ss, o);
    float inv = 1.0f / fmaxf(sqrtf(ss), 1e-12f);
    base[lane]      = a * inv * qscale[lane];
    base[lane + 32] = b * inv * qscale[lane + 32];
}

// ---------------- build K (l2-normalized * k_scale, incl. null) and V ----------------
__global__ __launch_bounds__(256)
void kv_build_kernel(const float* __restrict__ kv, const float* __restrict__ nullkv,
                     const float* __restrict__ kscale,
                     float* __restrict__ kout, float* __restrict__ vout)
{
    int w    = (blockIdx.x * 256 + threadIdx.x) >> 5;
    int lane = threadIdx.x & 31;
    if (w >= B_ * H_ * TK_) return;
    int bh = w / TK_;
    int t  = w - bh * TK_;
    int b  = bh >> 4, h = bh & 15;
    float k0, k1, v0, v1;
    if (t < T_) {
        const float* src = kv + (size_t)(b * T_ + t) * (2 * INNER_) + h * 64;
        k0 = src[lane];            k1 = src[lane + 32];
        v0 = src[INNER_ + lane];   v1 = src[INNER_ + lane + 32];
    } else {
        k0 = nullkv[lane];         k1 = nullkv[lane + 32];
        v0 = nullkv[64 + lane];    v1 = nullkv[64 + lane + 32];
    }
    float ss = k0*k0 + k1*k1;
    #pragma unroll
    for (int o = 16; o; o >>= 1) ss += __shfl_xor_sync(0xffffffffu, ss, o);
    float inv = 1.0f / fmaxf(sqrtf(ss), 1e-12f);
    size_t o = (size_t)w * 64;
    kout[o + lane]      = k0 * inv * kscale[lane];
    kout[o + lane + 32] = k1 * inv * kscale[lane + 32];
    vout[o + lane]      = v0;
    vout[o + lane + 32] = v1;
}

// ================== fused flash attention (tf32) ==================
// Grid: (N_/128, B_*H_). 256 threads = 8 warps, warp w owns rows w*16..w*16+15.
// KV processed in 5 chunks of 64 (covers 257 with masking). Online softmax.
// Dynamic smem: Ks[64][68] (tf32 [d][t]) + Vs[64][68] ([t][d]) + Ps[64][132] ([t][m], also Q staging [d][m]).
#define KS_OFF 0
#define VS_OFF (64*68)
#define PS_OFF (2*64*68)
#define FLASH_SMEM ((2*64*68 + 64*132) * 4)

__global__ __launch_bounds__(256)
void flash_kernel(const float* __restrict__ qv, const float* __restrict__ kk,
                  const float* __restrict__ vv, float* __restrict__ O)
{
    extern __shared__ unsigned smem[];
    unsigned* Ks = smem + KS_OFF;   // [d][t]  stride 68
    unsigned* Vs = smem + VS_OFF;   // [t][d]  stride 68
    unsigned* Ps = smem + PS_OFF;   // [t][m]  stride 132  (Q staging: [d][m])

    int tid = threadIdx.x, lane = tid & 31, warp = tid >> 5;
    int bh = blockIdx.y;
    int b = bh >> 4, h = bh & 15;
    int n0 = blockIdx.x * 128;
    const float* qb = qv + (size_t)(b * N_) * INNER_ + h * 64;
    const float* kb = kk + (size_t)bh * TK_ * D_;
    const float* vb = vv + (size_t)bh * TK_ * D_;
    float* Ob = O + (size_t)(b * N_) * INNER_ + h * 64;

    // ---- stage Q [128 x 64] into Ps as [d][m], then load fragments ----
    #pragma unroll
    for (int i = 0; i < 8; i++) {
        int l = tid + i * 256;          // 2048 float4 total
        int m = l >> 4, cq = l & 15;
        float4 v = *(const float4*)&qb[(size_t)(n0 + m) * INNER_ + cq*4];
        Ps[(cq*4+0)*132 + m] = f2tf32(v.x);
        Ps[(cq*4+1)*132 + m] = f2tf32(v.y);
        Ps[(cq*4+2)*132 + m] = f2tf32(v.z);
        Ps[(cq*4+3)*132 + m] = f2tf32(v.w);
    }
    __syncthreads();

    int m = warp * 16 + (lane >> 2);
    unsigned qf[8][4];
    #pragma unroll
    for (int kf = 0; kf < 8; kf++) {
        int ck = kf*8 + (lane & 3);
        qf[kf][0] = Ps[ck*132 + m];
        qf[kf][1] = Ps[ck*132 + m + 8];
        qf[kf][2] = Ps[(ck+4)*132 + m];
        qf[kf][3] = Ps[(ck+4)*132 + m + 8];
    }

    float m_run[2] = {-INFINITY, -INFINITY};
    float l_run[2] = {0.f, 0.f};
    float o[8][4] = {};

    for (int ch = 0; ch < 5; ch++) {
        int t0 = ch * 64;
        __syncthreads();                 // prev PV reads done; Q frags loaded
        // ---- stage K chunk -> Ks[d][t], V chunk -> Vs[t][d] ----
        #pragma unroll
        for (int i = 0; i < 4; i++) {
            int l = tid + i * 256;       // 1024 float4 each
            int tr = l >> 4, cq = l & 15;
            int t = t0 + tr;
            float4 k4 = make_float4(0.f,0.f,0.f,0.f);
            float4 v4 = make_float4(0.f,0.f,0.f,0.f);
            if (t < TK_) {
                k4 = *(const float4*)&kb[(size_t)t * 64 + cq*4];
                v4 = *(const float4*)&vb[(size_t)t * 64 + cq*4];
            }
            Ks[(cq*4+0)*68 + tr] = f2tf32(k4.x);
            Ks[(cq*4+1)*68 + tr] = f2tf32(k4.y);
            Ks[(cq*4+2)*68 + tr] = f2tf32(k4.z);
            Ks[(cq*4+3)*68 + tr] = f2tf32(k4.w);
            uint4 vw = make_uint4(f2tf32(v4.x), f2tf32(v4.y), f2tf32(v4.z), f2tf32(v4.w));
            *(uint4*)&Vs[tr*68 + cq*4] = vw;
        }
        __syncthreads();

        // ---- S = Q K^T (warp: 16 x 64) ----
        float s[8][4] = {};
        #pragma unroll
        for (int kf = 0; kf < 8; kf++) {
            int ck = kf*8 + (lane & 3);
            unsigned bf[8][2];
            #pragma unroll
            for (int nt = 0; nt < 8; nt++) {
                int n = nt*8 + (lane >> 2);
                bf[nt][0] = Ks[ck*68 + n];
                bf[nt][1] = Ks[(ck+4)*68 + n];
            }
            #pragma unroll
            for (int nt = 0; nt < 8; nt++)
                mma_tf32(s[nt], qf[kf], bf[nt]);
        }

        // ---- scale + mask + online softmax ----
        bool need_mask = (t0 + 64 > TK_);
        float cm[2] = {-INFINITY, -INFINITY};
        #pragma unroll
        for (int nt = 0; nt < 8; nt++) {
            int tcol = t0 + nt*8 + 2*(lane & 3);
            #pragma unroll
            for (int j = 0; j < 4; j++) {
                float v = s[nt][j] * 8.0f;
                if (need_mask && (tcol + (j & 1)) >= TK_) v = -INFINITY;
                s[nt][j] = v;
                int r = j >> 1;
                cm[r] = fmaxf(cm[r], v);
            }
        }
        #pragma unroll
        for (int ox = 1; ox <= 2; ox <<= 1) {
            cm[0] = fmaxf(cm[0], __shfl_xor_sync(0xffffffffu, cm[0], ox));
            cm[1] = fmaxf(cm[1], __shfl_xor_sync(0xffffffffu, cm[1], ox));
        }
        float mn[2] = {fmaxf(m_run[0], cm[0]), fmaxf(m_run[1], cm[1])};
        float alpha[2] = {expf(m_run[0] - mn[0]), expf(m_run[1] - mn[1])};
        float psum[2] = {0.f, 0.f};
        #pragma unroll
        for (int nt = 0; nt < 8; nt++) {
            int tl = nt*8 + 2*(lane & 3);
            float p0 = expf(s[nt][0] - mn[0]);
            float p1 = expf(s[nt][1] - mn[0]);
            float p2 = expf(s[nt][2] - mn[1]);
            float p3 = expf(s[nt][3] - mn[1]);
            psum[0] += p0 + p1;
            psum[1] += p2 + p3;
            Ps[tl*132 + m]         = f2tf32(p0);
            Ps[(tl+1)*132 + m]     = f2tf32(p1);
            Ps[tl*132 + m + 8]     = f2tf32(p2);
            Ps[(tl+1)*132 + m + 8] = f2tf32(p3);
        }
        #pragma unroll
        for (int ox = 1; ox <= 2; ox <<= 1) {
            psum[0] += __shfl_xor_sync(0xffffffffu, psum[0], ox);
            psum[1] += __shfl_xor_sync(0xffffffffu, psum[1], ox);
        }
        l_run[0] = l_run[0] * alpha[0] + psum[0];
        l_run[1] = l_run[1] * alpha[1] + psum[1];
        m_run[0] = mn[0];
        m_run[1] = mn[1];
        #pragma unroll
        for (int nt = 0; nt < 8; nt++) {
            o[nt][0] *= alpha[0]; o[nt][1] *= alpha[0];
            o[nt][2] *= alpha[1]; o[nt][3] *= alpha[1];
        }
        __syncthreads();

        // ---- O += P V (warp: 16 x 64) ----
        #pragma unroll
        for (int kf = 0; kf < 8; kf++) {
            int ck = kf*8 + (lane & 3);
            unsigned af[4];
            af[0] = Ps[ck*132 + m];
            af[1] = Ps[ck*132 + m + 8];
            af[2] = Ps[(ck+4)*132 + m];
            af[3] = Ps[(ck+4)*132 + m + 8];
            unsigned bf[8][2];
            #pragma unroll
            for (int nt = 0; nt < 8; nt++) {
                int n = nt*8 + (lane >> 2);
                bf[nt][0] = Vs[ck*68 + n];
                bf[nt][1] = Vs[(ck+4)*68 + n];
            }
            #pragma unroll
            for (int nt = 0; nt < 8; nt++)
                mma_tf32(o[nt], af, bf[nt]);
        }
    }

    // ---- final scale by 1/l and write ----
    float inv0 = 1.0f / l_run[0];
    float inv1 = 1.0f / l_run[1];
    int rowg = n0 + warp * 16 + (lane >> 2);
    #pragma unroll
    for (int nt = 0; nt < 8; nt++) {
        int col = nt*8 + 2*(lane & 3);
        *(float2*)&Ob[(size_t)rowg * INNER_ + col]       = make_float2(o[nt][0]*inv0, o[nt][1]*inv0);
        *(float2*)&Ob[(size_t)(rowg + 8) * INNER_ + col] = make_float2(o[nt][2]*inv1, o[nt][3]*inv1);
    }
}

// ---------------- launch ----------------
extern "C" void kernel_launch(void* const* d_in, const int* in_sizes, int n_in,
                              void* d_out, int out_size)
{
    const float* x      = (const float*)d_in[0];
    const float* ctx    = (const float*)d_in[1];
    const float* Wq     = (const float*)d_in[2];
    const float* Wkv    = (const float*)d_in[3];
    const float* Wo     = (const float*)d_in[4];
    const float* nullkv = (const float*)d_in[5];
    const float* qscale = (const float*)d_in[6];
    const float* kscale = (const float*)d_in[7];
    const float* ln_in_g  = (const float*)d_in[8];
    const float* ln_in_b  = (const float*)d_in[9];
    const float* ln_ctx_g = (const float*)d_in[10];
    const float* ln_ctx_b = (const float*)d_in[11];
    const float* ln_out_g = (const float*)d_in[12];
    const float* ln_out_b = (const float*)d_in[13];
    float* out = (float*)d_out;

    float *p_xn, *p_cn, *p_q, *p_kv, *p_k, *p_v, *p_ao, *p_pr;
    cudaGetSymbolAddress((void**)&p_xn, g_xn);
    cudaGetSymbolAddress((void**)&p_cn, g_cn);
    cudaGetSymbolAddress((void**)&p_q,  g_q);
    cudaGetSymbolAddress((void**)&p_kv, g_kv);
    cudaGetSymbolAddress((void**)&p_k,  g_k);
    cudaGetSymbolAddress((void**)&p_v,  g_v);
    cudaGetSymbolAddress((void**)&p_ao, g_ao);
    cudaGetSymbolAddress((void**)&p_pr, g_pr);

    static bool attr_set = false;
    if (!attr_set) {
        cudaFuncSetAttribute(flash_kernel, cudaFuncAttributeMaxDynamicSharedMemorySize, FLASH_SMEM);
        attr_set = true;
    }

    // 1-2: LayerNorms
    ln_kernel<<<ROWS_X, 256>>>(x,   ln_in_g,  ln_in_b,  p_xn);
    ln_kernel<<<ROWS_C, 256>>>(ctx, ln_ctx_g, ln_ctx_b, p_cn);
    // 3-4: projections (tf32 tensor cores)
    gemm_tc<<<dim3(INNER_/128,   ROWS_X/128), 256>>>(p_xn, Wq,  p_q,  DIMC, INNER_);
    gemm_tc<<<dim3(2*INNER_/128, ROWS_C/128), 256>>>(p_cn, Wkv, p_kv, DIMC, 2*INNER_);
    // 5: normalize q per head (in place)
    qnorm_kernel<<<(ROWS_X * H_) / 8, 256>>>(p_q, qscale);
    // 6: build K (normalized, incl null) and V
    kv_build_kernel<<<(B_*H_*TK_ + 7) / 8, 256>>>(p_kv, nullkv, kscale, p_k, p_v);
    // 7: fused attention (QK^T -> softmax -> PV)
    flash_kernel<<<dim3(N_/128, B_*H_), 256, FLASH_SMEM>>>(p_q, p_k, p_v, p_ao);
    // 8: output projection (tf32)
    gemm_tc<<<dim3(DIMC/128, ROWS_X/128), 256>>>(p_ao, Wo, p_pr, INNER_, DIMC);
    // 9: final LN -> d_out
    ln_kernel<<<ROWS_X, 256>>>(p_pr, ln_out_g, ln_out_b, out);
}